// round 15
// baseline (speedup 1.0000x reference)
#include <cuda_runtime.h>
#include <cuda_fp16.h>
#include <cstdint>

// ---------------- problem constants ----------------
#define BATCH    8192
#define DIMV     1024
#define KTOT     2048          // dimIn + dimOut
#define MT       128           // CTA M tile
#define NTG      16            // per-gate N per CTA (CTA covers 4x16 = 64 out cols)
#define NTILES   (DIMV / NTG)  // 64
#define MTILES   (BATCH / MT)  // 64
#define NTHREADS 128
#define KC       32            // K per pipeline stage (1 scratch ck32-tile)
#define NCHUNK   (KTOT / KC)   // 64
#define STAGES   4

// fp16 fragment-layout tiles (per 32-K stage)
#define A_TILE_B   (MT * KC * 2)           // 8192 bytes
#define B_TILE_B   (4 * NTG * KC * 2)      // 4096 bytes (4 gates x 16 cols)
#define STAGE_B    (A_TILE_B + B_TILE_B)   // 12288 bytes
#define SM_BIAS_B  (STAGES * STAGE_B)      // 49152
#define SMEM_TOTAL (SM_BIAS_B + 4 * NTG * 4)   // 49408 bytes/CTA -> 4 CTAs/SM

// ---------------- scratch: fp16, fragment-permuted copies (layouts unchanged) ----
// g_Xh: [mblk(64)][ck32(64)][mb(8)][k16(2)][lane(32)][4xb32]  (8192 B per ck32 tile)
// g_Wh: [g(4)][nblk(32)][ck32(64)][n8(4)][k16(2)][lane(32)][2xb32]  (2048 B per tile)
__device__ __half g_Xh[(size_t)BATCH * KTOT];     // 32 MB
__device__ __half g_Wh[(size_t)4 * KTOT * DIMV];  // 16 MB

// ---------------- helpers ----------------
static __device__ __forceinline__ uint32_t smem_u32(const void* p) {
    uint32_t a;
    asm("{ .reg .u64 t; cvta.to.shared.u64 t, %1; cvt.u32.u64 %0, t; }" : "=r"(a) : "l"(p));
    return a;
}
static __device__ __forceinline__ void cp16(uint32_t dst, const void* src) {
    asm volatile("cp.async.cg.shared.global [%0], [%1], 16;" :: "r"(dst), "l"(src));
}
static __device__ __forceinline__ void lds128(uint32_t addr, uint32_t* r) {
    asm volatile("ld.shared.v4.b32 {%0,%1,%2,%3}, [%4];"
                 : "=r"(r[0]), "=r"(r[1]), "=r"(r[2]), "=r"(r[3]) : "r"(addr));
}
static __device__ __forceinline__ void lds64(uint32_t addr, uint32_t* r) {
    asm volatile("ld.shared.v2.b32 {%0,%1}, [%2];" : "=r"(r[0]), "=r"(r[1]) : "r"(addr));
}
static __device__ __forceinline__ void mma_f16(float* c, const uint32_t* a, const uint32_t* b) {
    asm volatile(
        "mma.sync.aligned.m16n8k16.row.col.f32.f16.f16.f32 "
        "{%0,%1,%2,%3}, {%4,%5,%6,%7}, {%8,%9}, {%0,%1,%2,%3};"
        : "+f"(c[0]), "+f"(c[1]), "+f"(c[2]), "+f"(c[3])
        : "r"(a[0]), "r"(a[1]), "r"(a[2]), "r"(a[3]), "r"(b[0]), "r"(b[1]));
}
// hardware tanh (single MUFU op, sm_75+)
static __device__ __forceinline__ float tanh_hw(float v) {
    float r;
    asm("tanh.approx.f32 %0, %1;" : "=f"(r) : "f"(v));
    return r;
}
// sigmoid(x) = 0.5 * (1 + tanh(x/2))  -> one MUFU + 2 FMA
static __device__ __forceinline__ float sigm(float v) {
    return 0.5f * (1.0f + tanh_hw(0.5f * v));
}
static __device__ __forceinline__ uint32_t packh2(float lo, float hi) {
    __half2 t = __floats2half2_rn(lo, hi);
    return *reinterpret_cast<uint32_t*>(&t);
}

// ---------------- pre-pass (single launch): round to fp16 + permute ----------------
__global__ void prep_all(const float* __restrict__ x, const float* __restrict__ h,
                         const float* __restrict__ WI, const float* __restrict__ WF,
                         const float* __restrict__ WG, const float* __restrict__ WO) {
    const size_t totalX = (size_t)1 << 21;                   // 2M 16B units (32 MB)
    const size_t totalW = (size_t)1 << 21;                   // 2M 8B units (16 MB)
    for (size_t t = (size_t)blockIdx.x * blockDim.x + threadIdx.x; t < totalX + totalW;
         t += (size_t)gridDim.x * blockDim.x) {
        if (t < totalX) {
            const size_t u = t;
            const int lane = (int)(u & 31);
            const int k16  = (int)((u >> 5) & 1);
            const int mb   = (int)((u >> 6) & 7);
            const int ck   = (int)((u >> 9) & 63);
            const int mblk = (int)(u >> 15);                 // 0..63
            const int row  = mblk * 128 + mb * 16 + (lane >> 2);
            const int k    = ck * 32 + k16 * 16 + (lane & 3) * 2;
            const float* src = (k < DIMV) ? (x + k) : (h + k - DIMV);
            const size_t r0 = (size_t)row * DIMV, r8 = (size_t)(row + 8) * DIMV;
            uint4 o;
            o.x = packh2(src[r0],     src[r0 + 1]);
            o.y = packh2(src[r8],     src[r8 + 1]);
            o.z = packh2(src[r0 + 8], src[r0 + 9]);
            o.w = packh2(src[r8 + 8], src[r8 + 9]);
            ((uint4*)g_Xh)[u] = o;
        } else {
            const size_t u = t - totalX;
            const int lane = (int)(u & 31);
            const int k16  = (int)((u >> 5) & 1);
            const int n8   = (int)((u >> 6) & 3);
            const int ck   = (int)((u >> 8) & 63);
            const int nblk = (int)((u >> 14) & 31);
            const int g    = (int)(u >> 19);                 // 0..3
            const float* W = (g == 0) ? WI : (g == 1) ? WF : (g == 2) ? WG : WO;
            const int n = nblk * 32 + n8 * 8 + (lane >> 2);
            const int k = ck * 32 + k16 * 16 + (lane & 3) * 2;
            uint2 o;
            o.x = packh2(W[(size_t)k * DIMV + n],       W[(size_t)(k + 1) * DIMV + n]);
            o.y = packh2(W[(size_t)(k + 8) * DIMV + n], W[(size_t)(k + 9) * DIMV + n]);
            ((uint2*)g_Wh)[u] = o;
        }
    }
}

// ---------------- fused GEMM + LSTM kernel ----------------
// 1 CTA = 128 threads, 4 warps. 4 CTAs/SM -> each SMSP holds 4 warps from 4
// different CTAs (decorrelated barrier phases -> tensor pipe stays covered).
__global__ void __launch_bounds__(NTHREADS, 4) lstm_mma_kernel(
    const float* __restrict__ c,
    const float* __restrict__ bI, const float* __restrict__ bF,
    const float* __restrict__ bG, const float* __restrict__ bO,
    float* __restrict__ out_h, float* __restrict__ out_c)
{
    extern __shared__ __align__(16) char smem[];
    const uint32_t sbase = smem_u32(smem);
    const int tid  = threadIdx.x;
    const int lane = tid & 31;
    const int wid  = tid >> 5;
    const int nt    = blockIdx.x & (NTILES - 1);   // n fastest -> weights stay L2-resident
    const int mtile = blockIdx.x >> 6;             // 0..63
    const int m0 = mtile * MT;
    const int n0 = nt * NTG;
    const int nblk32 = nt >> 1, nbh = nt & 1;      // scratch 32-col block / 16-col half

    // stage biases (64 floats) past the pipeline stages
    if (tid < 4 * NTG) {
        int g = tid >> 4, j = tid & 15;
        const float* bsrc = (g == 0) ? bI : (g == 1) ? bF : (g == 2) ? bG : bO;
        ((float*)(smem + SM_BIAS_B))[tid] = bsrc[n0 + j];
    }

    // ---- stage loader: 768 16B chunks (512 A + 256 B); 6 cp16/thread ----
    auto loadStage = [&](int ck, int s) {
        const uint32_t As = sbase + (uint32_t)(s * STAGE_B);
        const uint32_t Bs = As + A_TILE_B;
        const char* Asrc = (const char*)g_Xh + ((size_t)mtile * 64 + ck) * 8192;
        #pragma unroll
        for (int r = 0; r < 4; r++) {            // 512 chunks of A (contiguous tile)
            int i = r * NTHREADS + tid;
            cp16(As + (uint32_t)i * 16, Asrc + (size_t)i * 16);
        }
        #pragma unroll
        for (int r = 0; r < 2; r++) {            // 256 chunks of B: 4 gates x 1KB half-tile
            int i = r * NTHREADS + tid;
            int g = i >> 6, w = i & 63;
            cp16(Bs + (uint32_t)(g * 1024 + w * 16),
                 (const char*)g_Wh + (((size_t)g * 32 + nblk32) * 64 + ck) * 2048
                                   + (size_t)(nbh * 1024 + w * 16));
        }
        asm volatile("cp.async.commit_group;" ::: "memory");
    };

    // prologue: fill 3 of 4 stages
    loadStage(0, 0);
    loadStage(1, 1);
    loadStage(2, 2);

    const int wm = wid & 1;     // 2 warps in M (64 rows each)
    const int wn = wid >> 1;    // 2 warps in N (8 cols per gate each)

    float acc[4][4][4];
    #pragma unroll
    for (int mt = 0; mt < 4; mt++)
        #pragma unroll
        for (int g = 0; g < 4; g++)
            #pragma unroll
            for (int e = 0; e < 4; e++) acc[mt][g][e] = 0.0f;

    // byte offsets within a stage
    const uint32_t a_base = (uint32_t)(wm * 4 * 1024 + lane * 16);       // + mt*1024 + ks*512
    const uint32_t b_base = (uint32_t)(A_TILE_B + wn * 512 + lane * 8);  // + g*1024 + ks*256

    for (int ck = 0; ck < NCHUNK; ck++) {
        asm volatile("cp.async.wait_group 2;" ::: "memory");
        __syncthreads();
        if (ck + 3 < NCHUNK) loadStage(ck + 3, (ck + 3) & 3);
        else asm volatile("cp.async.commit_group;" ::: "memory");

        const uint32_t stg = sbase + (uint32_t)((ck & 3) * STAGE_B);
        #pragma unroll
        for (int ks = 0; ks < 2; ks++) {
            uint32_t a[4][4], b[4][2];
            #pragma unroll
            for (int mt = 0; mt < 4; mt++)
                lds128(stg + a_base + ks * 512 + mt * 1024, a[mt]);
            #pragma unroll
            for (int g = 0; g < 4; g++)
                lds64(stg + b_base + ks * 256 + g * 1024, b[g]);
            #pragma unroll
            for (int mt = 0; mt < 4; mt++)
                #pragma unroll
                for (int g = 0; g < 4; g++)
                    mma_f16(acc[mt][g], a[mt], b[g]);
        }
    }
    __syncthreads();

    // ---- fused LSTM epilogue (hardware tanh: 1 MUFU per activation) ----
    const float* bias = (const float*)(smem + SM_BIAS_B);
    #pragma unroll
    for (int mt = 0; mt < 4; mt++) {
        #pragma unroll
        for (int er = 0; er < 2; er++) {
            const int m = m0 + wm * 64 + mt * 16 + (lane >> 2) + er * 8;
            const int nl = wn * 8 + 2 * (lane & 3);
            const size_t off = (size_t)m * DIMV + n0 + nl;
            const float2 cv = *(const float2*)(c + off);
            float2 hh, CC;
            #pragma unroll
            for (int cc = 0; cc < 2; cc++) {
                const int e = er * 2 + cc;
                float iv = acc[mt][0][e] + bias[0 * NTG + nl + cc];
                float fv = acc[mt][1][e] + bias[1 * NTG + nl + cc];
                float gv = acc[mt][2][e] + bias[2 * NTG + nl + cc];
                float ov = acc[mt][3][e] + bias[3 * NTG + nl + cc];
                float I = sigm(iv);
                float F = sigm(fv);
                float G = tanh_hw(gv);
                float O = sigm(ov);
                float Cv = F * (cc ? cv.y : cv.x) + I * G;
                float Hv = O * tanh_hw(Cv);
                if (cc) { hh.y = Hv; CC.y = Cv; } else { hh.x = Hv; CC.x = Cv; }
            }
            *(float2*)(out_h + off) = hh;
            *(float2*)(out_c + off) = CC;
        }
    }
}

// ---------------- launch ----------------
extern "C" void kernel_launch(void* const* d_in, const int* in_sizes, int n_in,
                              void* d_out, int out_size) {
    (void)in_sizes; (void)n_in; (void)out_size;
    const float* x  = (const float*)d_in[0];
    const float* h  = (const float*)d_in[1];
    const float* c  = (const float*)d_in[2];
    const float* WI = (const float*)d_in[3];
    const float* bI = (const float*)d_in[4];
    const float* WF = (const float*)d_in[5];
    const float* bF = (const float*)d_in[6];
    const float* WG = (const float*)d_in[7];
    const float* bG = (const float*)d_in[8];
    const float* WO = (const float*)d_in[9];
    const float* bO = (const float*)d_in[10];
    float* out_h = (float*)d_out;
    float* out_c = out_h + (size_t)BATCH * DIMV;

    prep_all<<<3072, 256>>>(x, h, WI, WF, WG, WO);

    cudaFuncSetAttribute(lstm_mma_kernel,
                         cudaFuncAttributeMaxDynamicSharedMemorySize, SMEM_TOTAL);
    lstm_mma_kernel<<<MTILES * NTILES, NTHREADS, SMEM_TOTAL>>>(
        c, bI, bF, bG, bO, out_h, out_c);
}

// round 16
// speedup vs baseline: 1.5290x; 1.5290x over previous
#include <cuda_runtime.h>
#include <cuda_fp16.h>
#include <cstdint>

// ---------------- problem constants ----------------
#define BATCH    8192
#define DIMV     1024
#define KTOT     2048          // dimIn + dimOut
#define MT       128           // CTA M tile
#define NTG      16            // per-gate N per CTA (CTA covers 4x16 = 64 out cols)
#define NTILES   (DIMV / NTG)  // 64
#define MTILES   (BATCH / MT)  // 64
#define NTHREADS 128
#define KC       32            // K per pipeline stage (1 scratch ck32-tile)
#define NCHUNK   (KTOT / KC)   // 64
#define STAGES   4

// fp16 fragment-layout tiles (per 32-K stage)
#define A_TILE_B   (MT * KC * 2)           // 8192 bytes
#define B_TILE_B   (4 * NTG * KC * 2)      // 4096 bytes (4 gates x 16 cols)
#define STAGE_B    (A_TILE_B + B_TILE_B)   // 12288 bytes
#define SM_BIAS_B  (STAGES * STAGE_B)      // 49152
#define SMEM_TOTAL (SM_BIAS_B + 4 * NTG * 4)   // 49408 bytes/CTA -> 4 CTAs/SM

// ---------------- scratch: fp16, fragment-permuted copies (layouts unchanged) ----
// g_Xh: [mblk(64)][ck32(64)][mb(8)][k16(2)][lane(32)][4xb32]  (8192 B per ck32 tile)
// g_Wh: [g(4)][nblk(32)][ck32(64)][n8(4)][k16(2)][lane(32)][2xb32]  (2048 B per tile)
__device__ __half g_Xh[(size_t)BATCH * KTOT];     // 32 MB
__device__ __half g_Wh[(size_t)4 * KTOT * DIMV];  // 16 MB

// ---------------- helpers ----------------
static __device__ __forceinline__ uint32_t smem_u32(const void* p) {
    uint32_t a;
    asm("{ .reg .u64 t; cvta.to.shared.u64 t, %1; cvt.u32.u64 %0, t; }" : "=r"(a) : "l"(p));
    return a;
}
static __device__ __forceinline__ void cp16(uint32_t dst, const void* src) {
    asm volatile("cp.async.cg.shared.global [%0], [%1], 16;" :: "r"(dst), "l"(src));
}
static __device__ __forceinline__ void lds128(uint32_t addr, uint32_t* r) {
    asm volatile("ld.shared.v4.b32 {%0,%1,%2,%3}, [%4];"
                 : "=r"(r[0]), "=r"(r[1]), "=r"(r[2]), "=r"(r[3]) : "r"(addr));
}
static __device__ __forceinline__ void lds64(uint32_t addr, uint32_t* r) {
    asm volatile("ld.shared.v2.b32 {%0,%1}, [%2];" : "=r"(r[0]), "=r"(r[1]) : "r"(addr));
}
static __device__ __forceinline__ void mma_f16(float* c, const uint32_t* a, const uint32_t* b) {
    asm volatile(
        "mma.sync.aligned.m16n8k16.row.col.f32.f16.f16.f32 "
        "{%0,%1,%2,%3}, {%4,%5,%6,%7}, {%8,%9}, {%0,%1,%2,%3};"
        : "+f"(c[0]), "+f"(c[1]), "+f"(c[2]), "+f"(c[3])
        : "r"(a[0]), "r"(a[1]), "r"(a[2]), "r"(a[3]), "r"(b[0]), "r"(b[1]));
}
// hardware tanh (single MUFU op, sm_75+)
static __device__ __forceinline__ float tanh_hw(float v) {
    float r;
    asm("tanh.approx.f32 %0, %1;" : "=f"(r) : "f"(v));
    return r;
}
// sigmoid(x) = 0.5 * (1 + tanh(x/2))  -> one MUFU + 2 FMA
static __device__ __forceinline__ float sigm(float v) {
    return 0.5f * (1.0f + tanh_hw(0.5f * v));
}
static __device__ __forceinline__ uint32_t packh2(float lo, float hi) {
    __half2 t = __floats2half2_rn(lo, hi);
    return *reinterpret_cast<uint32_t*>(&t);
}

// ---------------- pre-pass (single launch): round to fp16 + permute ----------------
__global__ void prep_all(const float* __restrict__ x, const float* __restrict__ h,
                         const float* __restrict__ WI, const float* __restrict__ WF,
                         const float* __restrict__ WG, const float* __restrict__ WO) {
    const size_t totalX = (size_t)1 << 21;                   // 2M 16B units (32 MB)
    const size_t totalW = (size_t)1 << 21;                   // 2M 8B units (16 MB)
    for (size_t t = (size_t)blockIdx.x * blockDim.x + threadIdx.x; t < totalX + totalW;
         t += (size_t)gridDim.x * blockDim.x) {
        if (t < totalX) {
            const size_t u = t;
            const int lane = (int)(u & 31);
            const int k16  = (int)((u >> 5) & 1);
            const int mb   = (int)((u >> 6) & 7);
            const int ck   = (int)((u >> 9) & 63);
            const int mblk = (int)(u >> 15);                 // 0..63
            const int row  = mblk * 128 + mb * 16 + (lane >> 2);
            const int k    = ck * 32 + k16 * 16 + (lane & 3) * 2;
            const float* src = (k < DIMV) ? (x + k) : (h + k - DIMV);
            const size_t r0 = (size_t)row * DIMV, r8 = (size_t)(row + 8) * DIMV;
            uint4 o;
            o.x = packh2(src[r0],     src[r0 + 1]);
            o.y = packh2(src[r8],     src[r8 + 1]);
            o.z = packh2(src[r0 + 8], src[r0 + 9]);
            o.w = packh2(src[r8 + 8], src[r8 + 9]);
            ((uint4*)g_Xh)[u] = o;
        } else {
            const size_t u = t - totalX;
            const int lane = (int)(u & 31);
            const int k16  = (int)((u >> 5) & 1);
            const int n8   = (int)((u >> 6) & 3);
            const int ck   = (int)((u >> 8) & 63);
            const int nblk = (int)((u >> 14) & 31);
            const int g    = (int)(u >> 19);                 // 0..3
            const float* W = (g == 0) ? WI : (g == 1) ? WF : (g == 2) ? WG : WO;
            const int n = nblk * 32 + n8 * 8 + (lane >> 2);
            const int k = ck * 32 + k16 * 16 + (lane & 3) * 2;
            uint2 o;
            o.x = packh2(W[(size_t)k * DIMV + n],       W[(size_t)(k + 1) * DIMV + n]);
            o.y = packh2(W[(size_t)(k + 8) * DIMV + n], W[(size_t)(k + 9) * DIMV + n]);
            ((uint2*)g_Wh)[u] = o;
        }
    }
}

// ---------------- fused GEMM + LSTM kernel ----------------
// 1 CTA = 128 threads, 4 warps. 4 CTAs/SM -> each SMSP holds 4 warps from 4
// different CTAs (decorrelated barrier phases -> tensor pipe stays covered).
__global__ void __launch_bounds__(NTHREADS, 4) lstm_mma_kernel(
    const float* __restrict__ c,
    const float* __restrict__ bI, const float* __restrict__ bF,
    const float* __restrict__ bG, const float* __restrict__ bO,
    float* __restrict__ out_h, float* __restrict__ out_c)
{
    extern __shared__ __align__(16) char smem[];
    const uint32_t sbase = smem_u32(smem);
    const int tid  = threadIdx.x;
    const int lane = tid & 31;
    const int wid  = tid >> 5;
    const int nt    = blockIdx.x & (NTILES - 1);   // n fastest -> weights stay L2-resident
    const int mtile = blockIdx.x >> 6;             // 0..63
    const int m0 = mtile * MT;
    const int n0 = nt * NTG;
    const int nblk32 = nt >> 1, nbh = nt & 1;      // scratch 32-col block / 16-col half

    // stage biases (64 floats) past the pipeline stages
    if (tid < 4 * NTG) {
        int g = tid >> 4, j = tid & 15;
        const float* bsrc = (g == 0) ? bI : (g == 1) ? bF : (g == 2) ? bG : bO;
        ((float*)(smem + SM_BIAS_B))[tid] = bsrc[n0 + j];
    }

    // ---- stage loader: 768 16B chunks (512 A + 256 B); 6 cp16/thread ----
    auto loadStage = [&](int ck, int s) {
        const uint32_t As = sbase + (uint32_t)(s * STAGE_B);
        const uint32_t Bs = As + A_TILE_B;
        const char* Asrc = (const char*)g_Xh + ((size_t)mtile * 64 + ck) * 8192;
        #pragma unroll
        for (int r = 0; r < 4; r++) {            // 512 chunks of A (contiguous tile)
            int i = r * NTHREADS + tid;
            cp16(As + (uint32_t)i * 16, Asrc + (size_t)i * 16);
        }
        #pragma unroll
        for (int r = 0; r < 2; r++) {            // 256 chunks of B: 4 gates x 1KB half-tile
            int i = r * NTHREADS + tid;
            int g = i >> 6, w = i & 63;
            cp16(Bs + (uint32_t)(g * 1024 + w * 16),
                 (const char*)g_Wh + (((size_t)g * 32 + nblk32) * 64 + ck) * 2048
                                   + (size_t)(nbh * 1024 + w * 16));
        }
        asm volatile("cp.async.commit_group;" ::: "memory");
    };

    // prologue: fill 3 of 4 stages
    loadStage(0, 0);
    loadStage(1, 1);
    loadStage(2, 2);

    const int wm = wid & 1;     // 2 warps in M (64 rows each)
    const int wn = wid >> 1;    // 2 warps in N (8 cols per gate each)

    float acc[4][4][4];
    #pragma unroll
    for (int mt = 0; mt < 4; mt++)
        #pragma unroll
        for (int g = 0; g < 4; g++)
            #pragma unroll
            for (int e = 0; e < 4; e++) acc[mt][g][e] = 0.0f;

    // byte offsets within a stage
    const uint32_t a_base = (uint32_t)(wm * 4 * 1024 + lane * 16);       // + mt*1024 + ks*512
    const uint32_t b_base = (uint32_t)(A_TILE_B + wn * 512 + lane * 8);  // + g*1024 + ks*256

    for (int ck = 0; ck < NCHUNK; ck++) {
        asm volatile("cp.async.wait_group 2;" ::: "memory");
        __syncthreads();
        if (ck + 3 < NCHUNK) loadStage(ck + 3, (ck + 3) & 3);
        else asm volatile("cp.async.commit_group;" ::: "memory");

        const uint32_t stg = sbase + (uint32_t)((ck & 3) * STAGE_B);
        #pragma unroll
        for (int ks = 0; ks < 2; ks++) {
            uint32_t a[4][4], b[4][2];
            #pragma unroll
            for (int mt = 0; mt < 4; mt++)
                lds128(stg + a_base + ks * 512 + mt * 1024, a[mt]);
            #pragma unroll
            for (int g = 0; g < 4; g++)
                lds64(stg + b_base + ks * 256 + g * 1024, b[g]);
            #pragma unroll
            for (int mt = 0; mt < 4; mt++)
                #pragma unroll
                for (int g = 0; g < 4; g++)
                    mma_f16(acc[mt][g], a[mt], b[g]);
        }
    }
    __syncthreads();

    // ---- fused LSTM epilogue (hardware tanh: 1 MUFU per activation) ----
    const float* bias = (const float*)(smem + SM_BIAS_B);
    #pragma unroll
    for (int mt = 0; mt < 4; mt++) {
        #pragma unroll
        for (int er = 0; er < 2; er++) {
            const int m = m0 + wm * 64 + mt * 16 + (lane >> 2) + er * 8;
            const int nl = wn * 8 + 2 * (lane & 3);
            const size_t off = (size_t)m * DIMV + n0 + nl;
            const float2 cv = *(const float2*)(c + off);
            float2 hh, CC;
            #pragma unroll
            for (int cc = 0; cc < 2; cc++) {
                const int e = er * 2 + cc;
                float iv = acc[mt][0][e] + bias[0 * NTG + nl + cc];
                float fv = acc[mt][1][e] + bias[1 * NTG + nl + cc];
                float gv = acc[mt][2][e] + bias[2 * NTG + nl + cc];
                float ov = acc[mt][3][e] + bias[3 * NTG + nl + cc];
                float I = sigm(iv);
                float F = sigm(fv);
                float G = tanh_hw(gv);
                float O = sigm(ov);
                float Cv = F * (cc ? cv.y : cv.x) + I * G;
                float Hv = O * tanh_hw(Cv);
                if (cc) { hh.y = Hv; CC.y = Cv; } else { hh.x = Hv; CC.x = Cv; }
            }
            *(float2*)(out_h + off) = hh;
            *(float2*)(out_c + off) = CC;
        }
    }
}

// ---------------- launch ----------------
extern "C" void kernel_launch(void* const* d_in, const int* in_sizes, int n_in,
                              void* d_out, int out_size) {
    (void)in_sizes; (void)n_in; (void)out_size;
    const float* x  = (const float*)d_in[0];
    const float* h  = (const float*)d_in[1];
    const float* c  = (const float*)d_in[2];
    const float* WI = (const float*)d_in[3];
    const float* bI = (const float*)d_in[4];
    const float* WF = (const float*)d_in[5];
    const float* bF = (const float*)d_in[6];
    const float* WG = (const float*)d_in[7];
    const float* bG = (const float*)d_in[8];
    const float* WO = (const float*)d_in[9];
    const float* bO = (const float*)d_in[10];
    float* out_h = (float*)d_out;
    float* out_c = out_h + (size_t)BATCH * DIMV;

    prep_all<<<3072, 256>>>(x, h, WI, WF, WG, WO);

    cudaFuncSetAttribute(lstm_mma_kernel,
                         cudaFuncAttributeMaxDynamicSharedMemorySize, SMEM_TOTAL);
    lstm_mma_kernel<<<MTILES * NTILES, NTHREADS, SMEM_TOTAL>>>(
        c, bI, bF, bG, bO, out_h, out_c);
}